// round 17
// baseline (speedup 1.0000x reference)
#include <cuda_runtime.h>

#define TDIM 200
#define PDIM 784
#define BDIM 256
#define PSPLIT 16
#define PCHUNK 49     // 784 / 16
#define BTILE 16
#define NUBLK (PSPLIT * (BDIM / BTILE))   // 256 u blocks
#define PI_F 3.14159265358979323846f

// k_uD dynamic smem (bytes): s_ri (49*200 packed pairs) 78400 | xv 6272
#define SMEM_BYTES (PCHUNK * TDIM * 8 + PCHUNK * BTILE * 8)

typedef unsigned long long ull;

// Scratch (no allocation allowed)
__device__ __align__(16) float2 g_D[TDIM * TDIM];    // [f][t], imag NEGATED, /T
__device__ __align__(16) float2 g_u[PSPLIT][BDIM * TDIM];  // p-split partials

// ---- packed f32x2 helpers ------------------------------------------------
__device__ __forceinline__ void upk2(ull v, float& x, float& y) {
    asm("mov.b64 {%0, %1}, %2;" : "=f"(x), "=f"(y) : "l"(v));
}
__device__ __forceinline__ void fma2(ull& acc, ull a, ull b) {
    asm("fma.rn.f32x2 %0, %1, %2, %0;" : "+l"(acc) : "l"(a), "l"(b));
}

// ---------------------------------------------------------------------------
// K1 (merged): flat grid 456, block 200 threads.
//   blocks [0, 256):   u[b][f] = sum_p x[b][p]v[p] * S[p][f]   (complex GEMM)
//   blocks [256, 456): f = blk-256. Block computes c[f] by tree reduction,
//                      then thread t writes D[f][t] — fully coalesced rows.
// ---------------------------------------------------------------------------
__global__ void __launch_bounds__(TDIM, 2) k_uD(const float* __restrict__ x,
                                                const float* __restrict__ v,
                                                const float* __restrict__ sre,
                                                const float* __restrict__ sim,
                                                const float* __restrict__ wre,
                                                const float* __restrict__ wim,
                                                const float* __restrict__ ere,
                                                const float* __restrict__ eim) {
    extern __shared__ __align__(16) float sm[];
    const int blk = blockIdx.x;
    const int tid = threadIdx.x;

    if (blk >= NUBLK) {
        // ---- D branch: block f; c[f] via reduction; coalesced row write --
        const int f = blk - NUBLK;
        float* rr = sm;            // [200]
        float* ri = sm + 256;      // [200]
        float2* c_sh = (float2*)(sm + 512);
        const int t = tid;         // doubles as tau for the reduction
        const int m = (f * t) % TDIM;               // exact twiddle index
        float ang = (2.0f * PI_F / TDIM) * (float)m;
        float si, co;
        sincosf(ang, &si, &co);
        {
            float xr = wre[t], xi = wim[t];
            rr[t] = xr * co + xi * si;   // Re(w[tau] * e^{-i ang})
            ri[t] = xi * co - xr * si;
        }
        __syncthreads();
        if (t < 100) { rr[t] += rr[t + 100]; ri[t] += ri[t + 100]; }
        __syncthreads();
        if (t < 50)  { rr[t] += rr[t + 50];  ri[t] += ri[t + 50]; }
        __syncthreads();
        if (t < 25)  { rr[t] += rr[t + 25];  ri[t] += ri[t + 25]; }
        __syncthreads();
        if (t < 32) {
            float vr = (t < 25) ? rr[t] : 0.f;
            float vi = (t < 25) ? ri[t] : 0.f;
#pragma unroll
            for (int off = 16; off; off >>= 1) {
                vr += __shfl_down_sync(0xffffffffu, vr, off);
                vi += __shfl_down_sync(0xffffffffu, vi, off);
            }
            if (t == 0) {
                float er = ere[f], ei = eim[f];
                *c_sh = make_float2(vr * er - vi * ei, vr * ei + vi * er);
            }
        }
        __syncthreads();
        float2 c = *c_sh;
        // D[f][t] = (Re, -Im) of c[f] * e^{+i ang} / T   (same sincos!)
        const float inv = 1.0f / TDIM;
        g_D[f * TDIM + t] = make_float2((c.x * co - c.y * si) * inv,
                                        -(c.x * si + c.y * co) * inv);
        return;
    }

    // ---- u branch (R11 measured-best mainloop, unchanged) ----
    ull*    s_ri = (ull*)sm;                              // [49*200] (re,im)
    float2* xv_s = (float2*)(sm + 2 * PCHUNK * TDIM);     // [49][16] (a,a)

    const int s  = blk >> 4;
    const int b0 = (blk & 15) * BTILE;
    const int p0 = s * PCHUNK;

    {
        const float4* sr4 = (const float4*)(sre + (size_t)p0 * TDIM);
        const float4* si4 = (const float4*)(sim + (size_t)p0 * TDIM);
        float4* dst = (float4*)s_ri;
        const int N4 = PCHUNK * TDIM / 4;   // 2450
#pragma unroll
        for (int it = 0; it < 13; it++) {
            int i = tid + it * TDIM;
            if (i < N4) {
                float4 r4 = sr4[i];
                float4 i4 = si4[i];
                dst[2 * i + 0] = make_float4(r4.x, i4.x, r4.y, i4.y);
                dst[2 * i + 1] = make_float4(r4.z, i4.z, r4.w, i4.w);
            }
        }
    }
#pragma unroll
    for (int it = 0; it < 4; it++) {
        int idx = tid + it * TDIM;
        if (idx < PCHUNK * BTILE) {
            int pp = idx >> 4, j = idx & 15;
            float a = x[(b0 + j) * PDIM + p0 + pp] * v[p0 + pp];
            xv_s[pp * BTILE + j] = make_float2(a, a);
        }
    }
    __syncthreads();

    const int f = tid;
    ull acc[BTILE];
#pragma unroll
    for (int j = 0; j < BTILE; j++) acc[j] = 0ull;

    const ulonglong2* xvb = (const ulonglong2*)xv_s;

#pragma unroll
    for (int pp = 0; pp < PCHUNK; pp++) {
        ull bpk = s_ri[pp * TDIM + f];
#pragma unroll
        for (int q = 0; q < 8; q++) {
            ulonglong2 a = xvb[pp * 8 + q];
            fma2(acc[2 * q + 0], a.x, bpk);
            fma2(acc[2 * q + 1], a.y, bpk);
        }
    }
#pragma unroll
    for (int j = 0; j < BTILE; j++) {
        float ur, ui_;
        upk2(acc[j], ur, ui_);
        g_u[s][(b0 + j) * TDIM + f] = make_float2(ur, ui_);
    }
}

// ---------------------------------------------------------------------------
// K2: r[b][t] = Re(sum_f u[b][f]*D[f][t]); chunk-max; 10x10 linear
// grid 128, block (200, 4) = 800 threads. ty-quarter covers f in [50*ty,
// 50*ty+50) for BOTH batches (disjoint D rows -> no redundant traffic),
// then 4-way cross-ty smem reduce. 10-deep LDG.64 prefetch pipeline.
// u-gather also split: each ty reduces 8 of the 16 p-splits for one batch.
// ---------------------------------------------------------------------------
__global__ void __launch_bounds__(4 * TDIM) k_out(const float* __restrict__ lw,
                                                  const float* __restrict__ lb,
                                                  float* __restrict__ out) {
    __shared__ __align__(16) float2 upart[4][TDIM];  // [ty][f] gather halves
    __shared__ __align__(16) ull u_sh[2][TDIM];      // [batch][f] (re,im)
    __shared__ float part[4][2][TDIM];               // [ty][batch][t]
    __shared__ float vals[2][TDIM];
    __shared__ float cm[2][10];
    const int t  = threadIdx.x;
    const int ty = threadIdx.y;
    const int b0 = blockIdx.x * 2;

    // gather: ty handles batch (ty&1), splits [8*(ty>>1), +8)
    {
        const int bb = ty & 1, s0 = (ty >> 1) * 8;
        float2 a = make_float2(0.f, 0.f);
#pragma unroll
        for (int s = 0; s < 8; s++) {
            float2 p = g_u[s0 + s][(b0 + bb) * TDIM + t];
            a.x += p.x; a.y += p.y;
        }
        upart[ty][t] = a;
    }
    __syncthreads();
    if (ty < 2) {
        float2 a = upart[ty][t], b = upart[ty + 2][t];
        ((float2*)u_sh[ty])[t] = make_float2(a.x + b.x, a.y + b.y);
    }
    __syncthreads();

    const ull* Dg  = (const ull*)g_D;     // packed (dre, -dim) at [f*200 + t]
    const ull* u0s = u_sh[0];
    const ull* u1s = u_sh[1];
    const int f0 = ty * 50;

    ull a0a = 0, a0b = 0, a1a = 0, a1b = 0;
    ull cur[10], nxt[10];
#pragma unroll
    for (int k = 0; k < 10; k++) cur[k] = Dg[(f0 + k) * TDIM + t];

    for (int g = 0; g < 5; g++) {
        if (g < 4) {
            const int fb = f0 + (g + 1) * 10;
#pragma unroll
            for (int k = 0; k < 10; k++) nxt[k] = Dg[(fb + k) * TDIM + t];
        }
        const int fb = f0 + g * 10;
#pragma unroll
        for (int k = 0; k < 10; k++) {
            ull uu0 = u0s[fb + k];         // LDS.64 broadcast
            ull uu1 = u1s[fb + k];
            if (k & 1) { fma2(a0b, uu0, cur[k]); fma2(a1b, uu1, cur[k]); }
            else       { fma2(a0a, uu0, cur[k]); fma2(a1a, uu1, cur[k]); }
        }
#pragma unroll
        for (int k = 0; k < 10; k++) cur[k] = nxt[k];
    }
    {
        float x0, y0, x1, y1;
        upk2(a0a, x0, y0); upk2(a0b, x1, y1);
        part[ty][0][t] = (x0 + y0) + (x1 + y1);   // partial Re-dot, batch 0
        upk2(a1a, x0, y0); upk2(a1b, x1, y1);
        part[ty][1][t] = (x0 + y0) + (x1 + y1);   // batch 1
    }
    __syncthreads();

    if (ty < 2) {
        float r = (part[0][ty][t] + part[1][ty][t]) +
                  (part[2][ty][t] + part[3][ty][t]);
        vals[ty][t] = sqrtf(fmaf(r, r, 1e-20f));
    }
    __syncthreads();

    if (ty == 0 && t < 20) {
        int bb = t / 10, cc = t % 10;
        float mx = 0.f;
#pragma unroll
        for (int k = 0; k < 20; k++) mx = fmaxf(mx, vals[bb][cc * 20 + k]);
        cm[bb][cc] = mx;
    }
    __syncthreads();

    if (ty == 0 && t < 20) {
        int bb = t / 10, cc = t % 10;
        float o = lb[cc];
#pragma unroll
        for (int c2 = 0; c2 < 10; c2++)
            o = fmaf(cm[bb][c2], lw[cc * 10 + c2], o);
        out[(b0 + bb) * 10 + cc] = o;
    }
}

// ---------------------------------------------------------------------------
extern "C" void kernel_launch(void* const* d_in, const int* in_sizes, int n_in,
                              void* d_out, int out_size) {
    const float* x   = (const float*)d_in[0];  // [256, 784]
    const float* v   = (const float*)d_in[1];  // [784]
    const float* sre = (const float*)d_in[2];  // [784, 200]
    const float* sim = (const float*)d_in[3];  // [784, 200]
    const float* ere = (const float*)d_in[4];  // [200]
    const float* eim = (const float*)d_in[5];  // [200]
    const float* wre = (const float*)d_in[6];  // [200]
    const float* wim = (const float*)d_in[7];  // [200]
    const float* lw  = (const float*)d_in[8];  // [10, 10]
    const float* lb  = (const float*)d_in[9];  // [10]
    float* out = (float*)d_out;                // [256, 10] float32

    cudaFuncSetAttribute(k_uD, cudaFuncAttributeMaxDynamicSharedMemorySize,
                         SMEM_BYTES);
    k_uD<<<NUBLK + TDIM, TDIM, SMEM_BYTES>>>(x, v, sre, sim,
                                             wre, wim, ere, eim);
    k_out<<<BDIM / 2, dim3(TDIM, 4)>>>(lw, lb, out);
}